// round 12
// baseline (speedup 1.0000x reference)
#include <cuda_runtime.h>

// FusedMultiPool: out[b,s,h,w] = max_k x[b, idx[s,k], h, w]
// x[32,256,64,64] f32, idx[128,8] i32, out[32,128,64,64] f32.
//
// R10: 48 warps/SM with R7's clean structure. 3 CTAs x 512 threads per SM,
// NBUF=2 (68 KB smem/CTA), fully-unrolled 8-sets-per-warp compute, exact
// 4-chunk staging, prescaled byte-offset idx. R7/R9 showed L1 is saturated
// while active (~24us busy = wavefront floor) but idle ~33%; R8 showed 48
// warps only helps with clean code. Three independently-barriered CTAs per
// SM cover each other's barrier/wait gaps.

#define BB 32
#define CC 256
#define HWP 4096                 // 64*64
#define SS 128
#define TT 32                    // hw strip width (floats); one tile = 32 KB
#define NTHREADS 512
#define NWARPS (NTHREADS / 32)       // 16
#define SETS_PER_WARP (SS / NWARPS)  // 8

#define NTILES ((HWP / TT) * BB)     // 4096 flat tiles (b*128 + strip)
#define GRID 444                     // 148 SMs x 3 CTAs
#define TILE_FLOATS (CC * TT)        // 8192
#define TILE_BYTES (TILE_FLOATS * 4) // 32768
#define NBUF 2
#define SMEM_BYTES (NBUF * TILE_BYTES + SS * 2 * 16)  // 64 KB bufs + 4 KB idx

__device__ __forceinline__ void cp_async16(void* smem_dst, const void* gmem_src)
{
    unsigned saddr = (unsigned)__cvta_generic_to_shared(smem_dst);
    asm volatile("cp.async.cg.shared.global [%0], [%1], 16;\n"
                 :: "r"(saddr), "l"(gmem_src));
}
#define CP_COMMIT() asm volatile("cp.async.commit_group;\n" ::: "memory")
#define CP_WAIT1()  asm volatile("cp.async.wait_group 1;\n" ::: "memory")

// Stage one 256x32-float tile (32 KB): 2048 x 16B chunks, exactly 4 per
// thread, fully coalesced (8 chunks = one 128B channel row).
__device__ __forceinline__ void prefetch_tile(float* buf, const float* __restrict__ x,
                                              int flat, int t)
{
    const int b     = flat >> 7;     // / (HWP/TT)
    const int strip = flat & 127;
    const char* src = reinterpret_cast<const char*>(
        x + (size_t)b * CC * HWP + strip * TT);
    char* dst = reinterpret_cast<char*>(buf);
    #pragma unroll
    for (int j = 0; j < (TILE_BYTES / 16) / NTHREADS; ++j) {   // 4
        int chunk = t + j * NTHREADS;
        int c = chunk >> 3;          // 8 chunks per channel row
        int q = chunk & 7;
        cp_async16(dst + chunk * 16, src + (size_t)c * (HWP * 4) + q * 16);
    }
}

__global__ void __launch_bounds__(NTHREADS, 3)
fmp_kernel(const float* __restrict__ x,
           const int*   __restrict__ idx,
           float*       __restrict__ out)
{
    extern __shared__ __align__(16) unsigned char smem_raw[];
    float* bufs = reinterpret_cast<float*>(smem_raw);                 // 2 tiles
    int4*  sidx = reinterpret_cast<int4*>(smem_raw + NBUF * TILE_BYTES);

    const int t    = threadIdx.x;
    const int lane = t & 31;
    const int warp = t >> 5;
    const int g    = blockIdx.x;

    // Stage index table once, pre-scaled to byte offsets (c * TT * 4).
    // Visible after the first in-loop __syncthreads(), before any compute.
    if (t < SS * 2) {
        int4 v = reinterpret_cast<const int4*>(idx)[t];
        v.x *= TT * 4; v.y *= TT * 4; v.z *= TT * 4; v.w *= TT * 4;
        sidx[t] = v;
    }

    const int n = (NTILES - 1 - g) / GRID + 1;   // 9 or 10 tiles for this CTA

    // Prologue: fills for tiles 0 and 1 in flight (groups G0, G1).
    prefetch_tile(bufs, x, g, t);
    CP_COMMIT();
    if (n > 1) prefetch_tile(bufs + TILE_FLOATS, x, g + GRID, t);
    CP_COMMIT();

    int cur = 0;
    for (int i = 0; i < n; ++i) {
        CP_WAIT1();          // my chunks of fill i landed (fill i+1 may pend)
        __syncthreads();     // everyone's chunks of fill i visible

        // Compute tile i: warp covers sets {8*warp .. 8*warp+7}.
        const char* __restrict__ bb =
            reinterpret_cast<const char*>(bufs + cur * TILE_FLOATS) + lane * 4;
        const int flat  = g + i * GRID;
        const int b     = flat >> 7;
        const int strip = flat & 127;
        float* outb = out + (size_t)b * SS * HWP + strip * TT + lane;

        #pragma unroll
        for (int it = 0; it < SETS_PER_WARP; ++it) {
            const int s = warp * SETS_PER_WARP + it;
            const int4 r0 = sidx[s * 2 + 0];     // pre-scaled byte offsets
            const int4 r1 = sidx[s * 2 + 1];

            float v0 = *reinterpret_cast<const float*>(bb + r0.x);
            float v1 = *reinterpret_cast<const float*>(bb + r0.y);
            float v2 = *reinterpret_cast<const float*>(bb + r0.z);
            float v3 = *reinterpret_cast<const float*>(bb + r0.w);
            float v4 = *reinterpret_cast<const float*>(bb + r1.x);
            float v5 = *reinterpret_cast<const float*>(bb + r1.y);
            float v6 = *reinterpret_cast<const float*>(bb + r1.z);
            float v7 = *reinterpret_cast<const float*>(bb + r1.w);

            float m = fmaxf(fmaxf(fmaxf(v0, v1), fmaxf(v2, v3)),
                            fmaxf(fmaxf(v4, v5), fmaxf(v6, v7)));

            outb[(size_t)s * HWP] = m;           // 128 B coalesced STG per warp
        }

        __syncthreads();     // all warps done reading buf[cur]; safe to refill

        if (i + 2 < n)
            prefetch_tile(bufs + cur * TILE_FLOATS, x, g + (i + 2) * GRID, t);
        CP_COMMIT();         // commit every iter to keep group counts aligned

        cur ^= 1;
    }
}

extern "C" void kernel_launch(void* const* d_in, const int* in_sizes, int n_in,
                              void* d_out, int out_size)
{
    const float* x   = (const float*)d_in[0];   // [32,256,64,64] f32
    const int*   idx = (const int*)d_in[1];     // [128,8] i32
    float*       out = (float*)d_out;           // [32,128,64,64] f32

    static bool attr_set = false;
    if (!attr_set) {
        cudaFuncSetAttribute(fmp_kernel,
                             cudaFuncAttributeMaxDynamicSharedMemorySize,
                             SMEM_BYTES);
        attr_set = true;
    }

    fmp_kernel<<<GRID, NTHREADS, SMEM_BYTES>>>(x, idx, out);
}

// round 13
// speedup vs baseline: 1.0638x; 1.0638x over previous
#include <cuda_runtime.h>

// FusedMultiPool: out[b,s,h,w] = max_k x[b, idx[s,k], h, w]
// x[32,256,64,64] f32, idx[128,8] i32, out[32,128,64,64] f32.
//
// R12 = R7 (proven champion: 34.7us ncu / 37.4us harness) + prescaled
// byte-offset index table. R8/R9/R10 all regressed by changing structure;
// the one component they validated is prescaling (kills 8 IMADs per set,
// ALU 19.7% -> ~13%, and shaves regs off the 64K RF boundary that was
// squeezing R7's 2nd CTA). Everything else is byte-identical to R7:
// 2 CTAs x 512 threads, NBUF=3 cp.async pipeline, ONE barrier per tile,
// fully unrolled 8-sets-per-warp compute.

#define BB 32
#define CC 256
#define HWP 4096                 // 64*64
#define SS 128
#define TT 32                    // hw strip width (floats); one tile = 32 KB
#define NTHREADS 512
#define NWARPS (NTHREADS / 32)       // 16
#define SETS_PER_WARP (SS / NWARPS)  // 8

#define NTILES ((HWP / TT) * BB)     // 4096 flat tiles (b*128 + strip)
#define GRID 296                     // 148 SMs x 2 CTAs
#define TILE_FLOATS (CC * TT)        // 8192
#define TILE_BYTES (TILE_FLOATS * 4) // 32768
#define NBUF 3
#define SMEM_BYTES (NBUF * TILE_BYTES + SS * 2 * 16)  // 96 KB bufs + 4 KB idx

__device__ __forceinline__ void cp_async16(void* smem_dst, const void* gmem_src)
{
    unsigned saddr = (unsigned)__cvta_generic_to_shared(smem_dst);
    asm volatile("cp.async.cg.shared.global [%0], [%1], 16;\n"
                 :: "r"(saddr), "l"(gmem_src));
}
#define CP_COMMIT() asm volatile("cp.async.commit_group;\n" ::: "memory")
#define CP_WAIT1()  asm volatile("cp.async.wait_group 1;\n" ::: "memory")

// Stage one 256x32-float tile (32 KB): 2048 x 16B chunks, exactly 4 per
// thread, fully coalesced (8 chunks = one 128B channel row).
__device__ __forceinline__ void prefetch_tile(float* buf, const float* __restrict__ x,
                                              int flat, int t)
{
    const int b     = flat >> 7;     // / (HWP/TT)
    const int strip = flat & 127;
    const char* src = reinterpret_cast<const char*>(
        x + (size_t)b * CC * HWP + strip * TT);
    char* dst = reinterpret_cast<char*>(buf);
    #pragma unroll
    for (int j = 0; j < (TILE_BYTES / 16) / NTHREADS; ++j) {   // 4
        int chunk = t + j * NTHREADS;
        int c = chunk >> 3;          // 8 chunks per channel row
        int q = chunk & 7;
        cp_async16(dst + chunk * 16, src + (size_t)c * (HWP * 4) + q * 16);
    }
}

__global__ void __launch_bounds__(NTHREADS, 2)
fmp_kernel(const float* __restrict__ x,
           const int*   __restrict__ idx,
           float*       __restrict__ out)
{
    extern __shared__ __align__(16) unsigned char smem_raw[];
    float* bufs = reinterpret_cast<float*>(smem_raw);                 // 3 tiles
    int4*  sidx = reinterpret_cast<int4*>(smem_raw + NBUF * TILE_BYTES);

    const int t    = threadIdx.x;
    const int lane = t & 31;
    const int warp = t >> 5;
    const int g    = blockIdx.x;

    // Stage index table once, PRE-SCALED to byte offsets (c * TT * 4).
    // Visible after the first in-loop __syncthreads(), before any compute.
    if (t < SS * 2) {
        int4 v = reinterpret_cast<const int4*>(idx)[t];
        v.x <<= 7; v.y <<= 7; v.z <<= 7; v.w <<= 7;   // * TT*4 = *128
        sidx[t] = v;
    }

    const int n = (NTILES - 1 - g) / GRID + 1;   // 13 or 14 tiles for this CTA

    // Prologue: tiles 0 and 1 in flight.
    prefetch_tile(bufs, x, g, t);
    CP_COMMIT();
    if (n > 1) prefetch_tile(bufs + TILE_FLOATS, x, g + GRID, t);
    CP_COMMIT();

    int cur = 0;                                  // buffer of tile i
    for (int i = 0; i < n; ++i) {
        CP_WAIT1();          // my chunks of tile i landed (tile i+1 may pend)
        __syncthreads();     // everyone's landed; buf of tile i-1 is free

        // Prefetch tile i+2 into the buffer freed by tile i-1.
        int nxt2 = cur + 2; if (nxt2 >= NBUF) nxt2 -= NBUF;
        if (i + 2 < n)
            prefetch_tile(bufs + nxt2 * TILE_FLOATS, x, g + (i + 2) * GRID, t);
        CP_COMMIT();

        // Compute tile i: warp covers sets {8*warp .. 8*warp+7}, lane <-> hw.
        const char* __restrict__ bb =
            reinterpret_cast<const char*>(bufs + cur * TILE_FLOATS) + lane * 4;
        const int flat  = g + i * GRID;
        const int b     = flat >> 7;
        const int strip = flat & 127;
        float* outb = out + (size_t)b * SS * HWP + strip * TT + lane;

        #pragma unroll
        for (int it = 0; it < SETS_PER_WARP; ++it) {
            const int s = warp * SETS_PER_WARP + it;
            const int4 r0 = sidx[s * 2 + 0];     // pre-scaled byte offsets
            const int4 r1 = sidx[s * 2 + 1];

            float v0 = *reinterpret_cast<const float*>(bb + r0.x);
            float v1 = *reinterpret_cast<const float*>(bb + r0.y);
            float v2 = *reinterpret_cast<const float*>(bb + r0.z);
            float v3 = *reinterpret_cast<const float*>(bb + r0.w);
            float v4 = *reinterpret_cast<const float*>(bb + r1.x);
            float v5 = *reinterpret_cast<const float*>(bb + r1.y);
            float v6 = *reinterpret_cast<const float*>(bb + r1.z);
            float v7 = *reinterpret_cast<const float*>(bb + r1.w);

            float m = fmaxf(fmaxf(fmaxf(v0, v1), fmaxf(v2, v3)),
                            fmaxf(fmaxf(v4, v5), fmaxf(v6, v7)));

            outb[(size_t)s * HWP] = m;           // 128 B coalesced STG per warp
        }

        if (++cur == NBUF) cur = 0;
    }
}

extern "C" void kernel_launch(void* const* d_in, const int* in_sizes, int n_in,
                              void* d_out, int out_size)
{
    const float* x   = (const float*)d_in[0];   // [32,256,64,64] f32
    const int*   idx = (const int*)d_in[1];     // [128,8] i32
    float*       out = (float*)d_out;           // [32,128,64,64] f32

    static bool attr_set = false;
    if (!attr_set) {
        cudaFuncSetAttribute(fmp_kernel,
                             cudaFuncAttributeMaxDynamicSharedMemorySize,
                             SMEM_BYTES);
        attr_set = true;
    }

    fmp_kernel<<<GRID, NTHREADS, SMEM_BYTES>>>(x, idx, out);
}